// round 5
// baseline (speedup 1.0000x reference)
#include <cuda_runtime.h>
#include <cstdint>

// out[i] = W[inputs[i] - 1];  N = 16384*200;  W: 200 floats.
// Probe idx_raw[1]: ==0 -> int64 indices, !=0 -> int32.
// int64 path: cp.async.bulk double-buffered pipeline (bulk DMA loads,
// conflict-free replicated-smem gather, streaming stores).

#define N_TOTAL    (16384 * 200)
#define MAX_RANKS  200
#define TPB        512
#define NCTAS      592                      // 148 SMs * 4 CTAs
#define EPC        1024                     // int64 elems per chunk
#define CHUNK_B    (EPC * 8)                // 8192 bytes
#define NCHUNKS    (N_TOTAL / EPC)          // 3200

__device__ __forceinline__ uint32_t smem_u32(const void* p) {
    uint32_t a;
    asm("{ .reg .u64 t; cvta.to.shared.u64 t, %1; cvt.u32.u64 %0, t; }"
        : "=r"(a) : "l"(p));
    return a;
}

__device__ __forceinline__ void mbar_init(uint32_t mbar, uint32_t count) {
    asm volatile("mbarrier.init.shared.b64 [%0], %1;" :: "r"(mbar), "r"(count) : "memory");
}

__device__ __forceinline__ void bulk_load(uint32_t dst, const void* src,
                                          uint32_t bytes, uint32_t mbar) {
    asm volatile("mbarrier.arrive.expect_tx.shared::cta.b64 _, [%0], %1;"
                 :: "r"(mbar), "r"(bytes) : "memory");
    asm volatile("cp.async.bulk.shared::cta.global.mbarrier::complete_tx::bytes "
                 "[%0], [%1], %2, [%3];"
                 :: "r"(dst), "l"(src), "r"(bytes), "r"(mbar) : "memory");
}

__device__ __forceinline__ void mbar_wait(uint32_t mbar, uint32_t parity) {
    asm volatile(
        "{\n\t.reg .pred P;\n\t"
        "WL_%=:\n\t"
        "mbarrier.try_wait.parity.acquire.cta.shared::cta.b64 P, [%0], %1, 0x989680;\n\t"
        "@!P bra WL_%=;\n\t}"
        :: "r"(mbar), "r"(parity) : "memory");
}

__global__ __launch_bounds__(TPB)
void bias_gather_kernel(const uint32_t* __restrict__ idx_raw,
                        const float* __restrict__ W,
                        float* __restrict__ out)
{
    // 32-way replicated W: sW[rank*32 + lane] -> bank == lane, conflict-free.
    __shared__ float sW[MAX_RANKS * 32];                        // 25600 B
    __shared__ __align__(16) unsigned long long ibuf[2][EPC];   // 2 x 8192 B
    __shared__ __align__(8)  unsigned long long mbar_s[2];

    const int tid  = threadIdx.x;
    const int lane = tid & 31;
    const int wid  = tid >> 5;
    const int bid  = blockIdx.x;

    const uint32_t probe = __ldcg(idx_raw + 1);   // 0 => int64 indices
    const uint32_t mb0 = smem_u32(&mbar_s[0]);
    const uint32_t mb1 = smem_u32(&mbar_s[1]);
    const uint32_t ib0 = smem_u32(&ibuf[0][0]);
    const uint32_t ib1 = smem_u32(&ibuf[1][0]);

    if (probe == 0u) {
        // ---------------- int64 path: bulk-DMA pipeline ----------------
        if (tid == 0) { mbar_init(mb0, 1); mbar_init(mb1, 1); }
        __syncthreads();

        const unsigned long long* __restrict__ idx8 =
            reinterpret_cast<const unsigned long long*>(idx_raw);

        if (tid == 0) {
            long long c0 = bid;
            if (c0 < NCHUNKS) bulk_load(ib0, idx8 + c0 * EPC, CHUNK_B, mb0);
            long long c1 = bid + NCTAS;
            if (c1 < NCHUNKS) bulk_load(ib1, idx8 + c1 * EPC, CHUNK_B, mb1);
        }

        // Fill replicated W while the first DMAs fly.
        #pragma unroll
        for (int k = wid; k < MAX_RANKS; k += TPB / 32) {
            float v = W[k];
            sW[k * 32 + lane] = v;
        }
        __syncthreads();

        float2* __restrict__ out2 = reinterpret_cast<float2*>(out);

        int k = 0;
        for (long long c = bid; c < NCHUNKS; c += NCTAS, k++) {
            const int      stage  = k & 1;
            const uint32_t parity = (k >> 1) & 1;
            mbar_wait(stage ? mb1 : mb0, parity);

            // 2 elems/thread: one conflict-free LDS.128
            const ulonglong2 v =
                *reinterpret_cast<const ulonglong2*>(&ibuf[stage][tid * 2]);
            float2 r;
            r.x = sW[((int)v.x - 1) * 32 + lane];
            r.y = sW[((int)v.y - 1) * 32 + lane];
            __stwt(out2 + c * (EPC / 2) + tid, r);

            __syncthreads();   // all lanes done reading ibuf[stage]
            if (tid == 0) {
                long long cn = c + 2 * NCTAS;
                if (cn < NCHUNKS)
                    bulk_load(stage ? ib1 : ib0, idx8 + cn * EPC, CHUNK_B,
                              stage ? mb1 : mb0);
            }
        }
    } else {
        // ---------------- int32 fallback: plain LDG loop ----------------
        #pragma unroll
        for (int k = wid; k < MAX_RANKS; k += TPB / 32) {
            float v = W[k];
            sW[k * 32 + lane] = v;
        }
        __syncthreads();

        const long long g      = (long long)bid * TPB + tid;
        const long long stride = (long long)NCTAS * TPB;
        const uint4* __restrict__ p = reinterpret_cast<const uint4*>(idx_raw);
        float4* __restrict__ out4   = reinterpret_cast<float4*>(out);

        for (long long u = g; u < N_TOTAL / 4; u += stride) {
            uint4 a = __ldcg(p + u);
            float4 r;
            r.x = sW[((int)a.x - 1) * 32 + lane];
            r.y = sW[((int)a.y - 1) * 32 + lane];
            r.z = sW[((int)a.z - 1) * 32 + lane];
            r.w = sW[((int)a.w - 1) * 32 + lane];
            __stwt(out4 + u, r);
        }
    }
}

extern "C" void kernel_launch(void* const* d_in, const int* in_sizes, int n_in,
                              void* d_out, int out_size)
{
    const uint32_t* idx = (const uint32_t*)d_in[0];  // inputs [16384, 200]
    const float*    W   = (const float*)d_in[1];     // [200, 1]
    float*          out = (float*)d_out;

    bias_gather_kernel<<<NCTAS, TPB>>>(idx, W, out);
}

// round 7
// speedup vs baseline: 1.0295x; 1.0295x over previous
#include <cuda_runtime.h>
#include <cstdint>

// out[i] = W[inputs[i] - 1];  N = 16384*200 = 3,276,800;  W: 200 floats.
// Index dtype probe: idx_raw[1]==0 -> int64 (high word of elem 0), else int32.
//
// 256-bit global ops (sm_103a) with explicit L2 policies:
//   - index loads:  ld.global.nc.L2::evict_last.v8.b32  (pin 26.2MB set in L2)
//   - out stores:   st.global.L2::evict_first.v8.b32    (stream past L2)
// 8 output elems / thread, exact grid (no tail): 800 * 512 * 8 = N.

#define N_TOTAL   (16384 * 200)
#define MAX_RANKS 200
#define TPB       512
#define NBLK      (N_TOTAL / (TPB * 8))   // 800

struct V8 { uint32_t r0,r1,r2,r3,r4,r5,r6,r7; };

__device__ __forceinline__ V8 ldg_pin8(const void* p) {
    V8 v;
    asm volatile("ld.global.nc.L2::evict_last.v8.b32 "
                 "{%0,%1,%2,%3,%4,%5,%6,%7}, [%8];"
                 : "=r"(v.r0), "=r"(v.r1), "=r"(v.r2), "=r"(v.r3),
                   "=r"(v.r4), "=r"(v.r5), "=r"(v.r6), "=r"(v.r7)
                 : "l"(p));
    return v;
}

__device__ __forceinline__ void stg_stream8(void* p, const float* f) {
    asm volatile("st.global.L2::evict_first.v8.b32 "
                 "[%0], {%1,%2,%3,%4,%5,%6,%7,%8};"
                 :: "l"(p),
                    "f"(f[0]), "f"(f[1]), "f"(f[2]), "f"(f[3]),
                    "f"(f[4]), "f"(f[5]), "f"(f[6]), "f"(f[7])
                 : "memory");
}

__global__ __launch_bounds__(TPB)
void bias_gather_kernel(const uint32_t* __restrict__ idx_raw,
                        const float* __restrict__ W,
                        float* __restrict__ out)
{
    // 32-way replicated W: sW[rank*32 + lane] -> bank == lane, conflict-free.
    __shared__ float sW[MAX_RANKS * 32];

    const int tid  = threadIdx.x;
    const int lane = tid & 31;
    const int wid  = tid >> 5;

    const uint32_t probe = idx_raw[1];   // 0 => int64 indices

    #pragma unroll
    for (int k = wid; k < MAX_RANKS; k += TPB / 32) {
        float v = W[k];                  // warp-uniform addr: 1 sector
        sW[k * 32 + lane] = v;           // conflict-free STS
    }
    __syncthreads();

    // Unit = 8 output elements. Global unit id:
    const long long u = (long long)blockIdx.x * TPB + tid;   // < 409,600

    float r[8];
    if (probe == 0u) {
        // int64: 8 indices = 64B = two v8.b32 loads; low words at even regs.
        const char* base = reinterpret_cast<const char*>(idx_raw) + u * 64;
        V8 a = ldg_pin8(base);
        V8 b = ldg_pin8(base + 32);
        r[0] = sW[((int)a.r0 - 1) * 32 + lane];
        r[1] = sW[((int)a.r2 - 1) * 32 + lane];
        r[2] = sW[((int)a.r4 - 1) * 32 + lane];
        r[3] = sW[((int)a.r6 - 1) * 32 + lane];
        r[4] = sW[((int)b.r0 - 1) * 32 + lane];
        r[5] = sW[((int)b.r2 - 1) * 32 + lane];
        r[6] = sW[((int)b.r4 - 1) * 32 + lane];
        r[7] = sW[((int)b.r6 - 1) * 32 + lane];
    } else {
        // int32: 8 indices = 32B = one v8.b32 load.
        const char* base = reinterpret_cast<const char*>(idx_raw) + u * 32;
        V8 a = ldg_pin8(base);
        r[0] = sW[((int)a.r0 - 1) * 32 + lane];
        r[1] = sW[((int)a.r1 - 1) * 32 + lane];
        r[2] = sW[((int)a.r2 - 1) * 32 + lane];
        r[3] = sW[((int)a.r3 - 1) * 32 + lane];
        r[4] = sW[((int)a.r4 - 1) * 32 + lane];
        r[5] = sW[((int)a.r5 - 1) * 32 + lane];
        r[6] = sW[((int)a.r6 - 1) * 32 + lane];
        r[7] = sW[((int)a.r7 - 1) * 32 + lane];
    }

    stg_stream8(reinterpret_cast<char*>(out) + u * 32, r);
}

extern "C" void kernel_launch(void* const* d_in, const int* in_sizes, int n_in,
                              void* d_out, int out_size)
{
    const uint32_t* idx = (const uint32_t*)d_in[0];  // inputs [16384, 200]
    const float*    W   = (const float*)d_in[1];     // [200, 1]
    float*          out = (float*)d_out;

    bias_gather_kernel<<<NBLK, TPB>>>(idx, W, out);
}